// round 17
// baseline (speedup 1.0000x reference)
#include <cuda_runtime.h>
#include <cstdint>

// ReadingLayerReLU: mma.sync tf32 (raw fp32 operands, RZ-truncation + bias
// correction) + ldmatrix + TMA bulk fills + 3-stage producer/consumer
// mbarrier pipeline with NO CTA-wide barriers in the mainloop.
// 128x128 block tile, 256 threads (8 warps, 4x2, 32x64 warp tile), BK=32,
// 3 stages, 2 CTAs/SM. Rotating producer warp issues refills.
// key = relu(x @ W^T)        : M=16384, N=256,  K=256
// val[b] = key[b] @ mem[b]^T : M=2048,  N=1024, K=256, batch=8

#define BM 128
#define BN 128
#define BK 32
#define LDSS 36            // row stride (words) = 144 B: 16B-aligned, LDSM conflict-free
#define TW (BM * LDSS)     // 4608 words per tile
#define STW (2 * TW)       // 9216 words per stage
#define NSTAGE 3
#define SMEM_BYTES (NSTAGE * STW * 4)   // 110592
#define STAGE_TX (2 * BM * BK * 4)      // 32768 bytes per stage

#define PROD_SCALE 1.0009765625f        // 1 + 2^-10 (E[RZ trunc loss] correction)

__device__ __forceinline__ uint32_t s2u(const void* p) {
    uint32_t a;
    asm("{ .reg .u64 t; cvta.to.shared.u64 t, %1; cvt.u32.u64 %0, t; }" : "=r"(a) : "l"(p));
    return a;
}

__device__ __forceinline__ void bulk128(uint32_t dst, const void* src, uint32_t mbar) {
    asm volatile(
        "cp.async.bulk.shared::cluster.global.mbarrier::complete_tx::bytes "
        "[%0], [%1], 128, [%2];"
        :: "r"(dst), "l"(src), "r"(mbar) : "memory");
}

__device__ __forceinline__ void ldsm4(uint32_t& r0, uint32_t& r1, uint32_t& r2, uint32_t& r3,
                                      uint32_t addr) {
    asm volatile("ldmatrix.sync.aligned.m8n8.x4.shared.b16 {%0,%1,%2,%3}, [%4];"
                 : "=r"(r0), "=r"(r1), "=r"(r2), "=r"(r3) : "r"(addr));
}

#define MBAR_WAIT(a, par) do {                                                    \
    uint32_t _m = (a), _p = (par), _d;                                            \
    asm volatile("{\n\t.reg .pred p;\n\t"                                         \
        "mbarrier.try_wait.parity.acquire.cta.shared::cta.b64 p, [%1], %2;\n\t"   \
        "selp.b32 %0, 1, 0, p;\n\t}"                                              \
        : "=r"(_d) : "r"(_m), "r"(_p) : "memory");                                \
    if (!_d) {                                                                    \
        asm volatile("{\n\t.reg .pred P1;\n\t"                                    \
        "WL_%=:\n\t"                                                              \
        "mbarrier.try_wait.parity.acquire.cta.shared::cta.b64 P1, [%0], %1, 0x989680;\n\t" \
        "@P1 bra.uni WD_%=;\n\t"                                                  \
        "bra.uni WL_%=;\n\t"                                                      \
        "WD_%=:\n\t}" :: "r"(_m), "r"(_p) : "memory");                            \
    }                                                                             \
} while (0)

#define MBAR_ARRIVE(a) \
    asm volatile("mbarrier.arrive.shared.b64 _, [%0];" :: "r"(a) : "memory")
#define MBAR_EXPECT(a, n) \
    asm volatile("mbarrier.arrive.expect_tx.shared.b64 _, [%0], %1;" \
                 :: "r"(a), "r"((uint32_t)(n)) : "memory")

template<bool RELU>
__global__ __launch_bounds__(256, 2)
void tf32_mma_nt(const float* __restrict__ A, const float* __restrict__ B,
                 float* __restrict__ C, int K, int N,
                 long sA, long sB, long sC)
{
    extern __shared__ uint32_t smem[];
    __shared__ __align__(8) unsigned long long mbFull[NSTAGE];
    __shared__ __align__(8) unsigned long long mbEmpty[NSTAGE];

    const int tid  = threadIdx.x;
    const int lane = tid & 31;
    const int warp = tid >> 5;
    const int wm   = warp >> 1;    // 0..3 -> M offset wm*32
    const int wn   = warp & 1;     // 0..1 -> N offset wn*64

    A += (long)blockIdx.z * sA + (long)blockIdx.y * BM * K;
    B += (long)blockIdx.z * sB + (long)blockIdx.x * BN * K;
    C += (long)blockIdx.z * sC;

    const uint32_t sbase = s2u(smem);
    uint32_t full[NSTAGE], empt[NSTAGE];
    #pragma unroll
    for (int i = 0; i < NSTAGE; i++) {
        full[i] = s2u(&mbFull[i]);
        empt[i] = s2u(&mbEmpty[i]);
    }

    // Fill mapping: virtual row r in [0,256): r<128 -> A row r; else B row r-128.
    const int myrow = tid;
    const float* gsrcT = (myrow < BM ? A + (long)myrow * K
                                     : B + (long)(myrow - BM) * K);
    const uint32_t dstT = (uint32_t)((myrow < BM ? myrow * LDSS
                                                 : TW + (myrow - BM) * LDSS)) * 4u;

    // LDSM lane address bases (byte offsets within a stage)
    const int la_rowA = wm * 32 + ((lane >> 3) & 1) * 8 + (lane & 7);
    const int la_colA = (lane >> 4) * 4;
    const uint32_t aBase = (uint32_t)(la_rowA * LDSS + la_colA) * 4u;
    const int la_rowB = wn * 64 + (lane >> 4) * 8 + (lane & 7);
    const int la_colB = ((lane >> 3) & 1) * 4;
    const uint32_t bBase = (uint32_t)(la_rowB * LDSS + la_colB) * 4u + (uint32_t)TW * 4u;

    const int nchunks = K / BK;    // 8

    if (tid == 0) {
        #pragma unroll
        for (int i = 0; i < NSTAGE; i++) {
            asm volatile("mbarrier.init.shared.b64 [%0], 1;" :: "r"(full[i]) : "memory");
            asm volatile("mbarrier.init.shared.b64 [%0], 8;" :: "r"(empt[i]) : "memory");
        }
    }
    __syncthreads();

    // Prologue: fill stages 0..2 (chunks 0..2); every thread copies its row.
    if (tid == 0) {
        #pragma unroll
        for (int s = 0; s < NSTAGE; s++) MBAR_EXPECT(full[s], STAGE_TX);
    }
    #pragma unroll
    for (int s = 0; s < NSTAGE; s++)
        bulk128(sbase + (uint32_t)(s * STW) * 4u + dstT, gsrcT + s * BK, full[s]);

    float acc[2][8][4];
    #pragma unroll
    for (int mi = 0; mi < 2; mi++)
        #pragma unroll
        for (int ni = 0; ni < 8; ni++)
            #pragma unroll
            for (int j = 0; j < 4; j++)
                acc[mi][ni][j] = 0.0f;

    #pragma unroll 1
    for (int kc = 0; kc < nchunks; kc++) {
        const int s   = kc % 3;
        const int par = (kc / 3) & 1;

        // consume: lane0 waits, warp released by syncwarp
        if (lane == 0) MBAR_WAIT(full[s], par);
        __syncwarp();

        const uint32_t stg = sbase + (uint32_t)(s * STW) * 4u;

        #pragma unroll
        for (int ks = 0; ks < 4; ks++) {
            const uint32_t kByte = (uint32_t)(ks * 8) * 4u;
            uint32_t af[2][4], bf[8][2];
            #pragma unroll
            for (int mi = 0; mi < 2; mi++)
                ldsm4(af[mi][0], af[mi][1], af[mi][2], af[mi][3],
                      stg + aBase + (uint32_t)(mi * 16 * LDSS) * 4u + kByte);
            #pragma unroll
            for (int j = 0; j < 4; j++)
                ldsm4(bf[2 * j][0], bf[2 * j][1], bf[2 * j + 1][0], bf[2 * j + 1][1],
                      stg + bBase + (uint32_t)(j * 16 * LDSS) * 4u + kByte);

            if (ks == 3) {           // all reads of this stage issued
                __syncwarp();
                if (lane == 0) MBAR_ARRIVE(empt[s]);
            }

            #pragma unroll
            for (int mi = 0; mi < 2; mi++)
                #pragma unroll
                for (int ni = 0; ni < 8; ni++)
                    asm volatile(
                        "mma.sync.aligned.m16n8k8.row.col.f32.tf32.tf32.f32 "
                        "{%0,%1,%2,%3}, {%4,%5,%6,%7}, {%8,%9}, {%0,%1,%2,%3};"
                        : "+f"(acc[mi][ni][0]), "+f"(acc[mi][ni][1]),
                          "+f"(acc[mi][ni][2]), "+f"(acc[mi][ni][3])
                        : "r"(af[mi][0]), "r"(af[mi][1]), "r"(af[mi][2]), "r"(af[mi][3]),
                          "r"(bf[ni][0]), "r"(bf[ni][1]));
        }

        // producer: warp kc refills stage s with chunk kc+3 after all 8 warps
        // arrived on empty for chunk kc.
        if (warp == kc && kc + NSTAGE < nchunks) {
            if (lane == 0) {
                MBAR_WAIT(empt[s], par);
                MBAR_EXPECT(full[s], STAGE_TX);
            }
            __syncwarp();
            #pragma unroll
            for (int j = 0; j < 8; j++) {
                const int r = lane * 8 + j;
                const float* src = (r < BM ? A + (long)r * K
                                           : B + (long)(r - BM) * K) + (kc + NSTAGE) * BK;
                const uint32_t d = stg + (uint32_t)((r < BM ? r * LDSS
                                                            : TW + (r - BM) * LDSS)) * 4u;
                bulk128(d, src, full[s]);
            }
        }
    }

    // Epilogue: bias-correct, optional ReLU, store.
    #pragma unroll
    for (int mi = 0; mi < 2; mi++) {
        const long row = (long)blockIdx.y * BM + wm * 32 + mi * 16 + (lane >> 2);
        #pragma unroll
        for (int ni = 0; ni < 8; ni++) {
            const long col = (long)blockIdx.x * BN + wn * 64 + ni * 8 + (lane & 3) * 2;
            float2 v0, v1;
            v0.x = acc[mi][ni][0] * PROD_SCALE;
            v0.y = acc[mi][ni][1] * PROD_SCALE;
            v1.x = acc[mi][ni][2] * PROD_SCALE;
            v1.y = acc[mi][ni][3] * PROD_SCALE;
            if (RELU) {
                v0.x = fmaxf(v0.x, 0.0f); v0.y = fmaxf(v0.y, 0.0f);
                v1.x = fmaxf(v1.x, 0.0f); v1.y = fmaxf(v1.y, 0.0f);
            }
            *(float2*)(C + row * N + col)       = v0;
            *(float2*)(C + (row + 8) * N + col) = v1;
        }
    }
}

extern "C" void kernel_launch(void* const* d_in, const int* in_sizes, int n_in,
                              void* d_out, int out_size)
{
    (void)in_sizes; (void)n_in; (void)out_size;

    const float* x   = (const float*)d_in[0];  // (8,2048,256)
    const float* mem = (const float*)d_in[1];  // (8,1024,256)
    const float* W   = (const float*)d_in[2];  // (256,256)

    float* key = (float*)d_out;                      // 16384*256
    float* val = (float*)d_out + (long)16384 * 256;  // 16384*1024

    static int configured = 0;
    if (!configured) {
        cudaFuncSetAttribute(tf32_mma_nt<true>,
                             cudaFuncAttributeMaxDynamicSharedMemorySize, SMEM_BYTES);
        cudaFuncSetAttribute(tf32_mma_nt<false>,
                             cudaFuncAttributeMaxDynamicSharedMemorySize, SMEM_BYTES);
        configured = 1;
    }

    // GEMM 1: key = relu(x @ W^T)  M=16384 N=256 K=256 -> grid (2,128)
    {
        dim3 grid(256 / BN, 16384 / BM, 1);
        tf32_mma_nt<true><<<grid, 256, SMEM_BYTES>>>(x, W, key, 256, 256, 0, 0, 0);
    }
    // GEMM 2: val[b] = key[b] @ mem[b]^T  M=2048 N=1024 K=256, batch 8 -> grid (8,16,8)
    {
        dim3 grid(1024 / BN, 2048 / BM, 8);
        tf32_mma_nt<false><<<grid, 256, SMEM_BYTES>>>(
            key, mem, val, 256, 1024,
            (long)2048 * 256, (long)1024 * 256, (long)2048 * 1024);
    }
}